// round 3
// baseline (speedup 1.0000x reference)
#include <cuda_runtime.h>
#include <math.h>
#include <float.h>

// Problem constants
#define NTOT 65536          // B*H*W
#define CDIM 512            // channels / key dim
#define MDIM 512            // number of memory slots
#define HWDIM 4096          // H*W
#define BDIM 16

// Output packing offsets (flat concat of the returned tuple, fp32)
#define OFF_UQ   0LL
#define OFF_UM   67108864LL           // 16*1024*4096
#define OFF_SQ   67371008LL           // + 512*512
#define OFF_SM   100925440LL          // + 65536*512
#define OFF_SEP  134479872LL          // + 65536*512
#define OFF_COMP 134479873LL

// ---------------- device scratch (no allocations allowed) ----------------
__device__ float  g_qr[(size_t)NTOT * CDIM];      // 128 MB normalized query rows
__device__ float  g_score[(size_t)NTOT * MDIM];   // 128 MB score, reused for concat_memory
__device__ float  g_cmax[MDIM];
__device__ float  g_csum[MDIM];
__device__ float  g_w[NTOT];
__device__ int    g_gi[NTOT];
__device__ int    g_count[MDIM];
__device__ int    g_offset[MDIM + 1];
__device__ int    g_cursor[MDIM];
__device__ int    g_list[NTOT];
__device__ double g_comp, g_sep;

// ---------------- helpers ----------------
__device__ __forceinline__ void atomicMaxF(float* addr, float val) {
    int* ia = (int*)addr;
    int old = *ia;
    while (__int_as_float(old) < val) {
        int assumed = old;
        old = atomicCAS(ia, assumed, __float_as_int(val));
        if (old == assumed) break;
    }
}

// ---------------- init ----------------
__global__ void k_init() {
    int t = blockIdx.x * blockDim.x + threadIdx.x;
    if (t < MDIM) { g_cmax[t] = -FLT_MAX; g_csum[t] = 0.0f; g_count[t] = 0; }
    if (t == 0) { g_comp = 0.0; g_sep = 0.0; }
}

// ---------------- L2 normalize over channels + transpose to (N, C) ----------------
// One block handles 16 consecutive (b,hw) positions; tile of C x 16 in smem.
__global__ void __launch_bounds__(256) k_normalize(const float* __restrict__ query) {
    __shared__ float s[CDIM * 17];
    __shared__ float psum[256];
    __shared__ float rn[16];
    int p0 = blockIdx.x * 16;               // global (b,hw) position
    int b = p0 >> 12;
    int hw0 = p0 & 4095;
    const float* qb = query + (size_t)b * CDIM * HWDIM + hw0;
    int tid = threadIdx.x;
    #pragma unroll
    for (int it = 0; it < 32; it++) {
        int i = it * 256 + tid;
        int c = i >> 4, j = i & 15;
        s[c * 17 + j] = qb[(size_t)c * HWDIM + j];
    }
    __syncthreads();
    {
        int j = tid & 15, g = tid >> 4;
        float acc = 0.0f;
        #pragma unroll
        for (int cc = 0; cc < 32; cc++) {
            float v = s[(g * 32 + cc) * 17 + j];
            acc += v * v;
        }
        psum[tid] = acc;
    }
    __syncthreads();
    if (tid < 16) {
        float tot = 0.0f;
        #pragma unroll
        for (int g = 0; g < 16; g++) tot += psum[g * 16 + tid];
        rn[tid] = 1.0f / fmaxf(sqrtf(tot), 1e-12f);
    }
    __syncthreads();
    #pragma unroll
    for (int it = 0; it < 32; it++) {
        int i = it * 256 + tid;
        int c = i & 511, j = i >> 9;
        g_qr[(size_t)(p0 + j) * CDIM + c] = s[c * 17 + j] * rn[j];
    }
}

// ---------------- SGEMM 128x128x16, 256 threads, 8x8 per thread ----------------
// TRANSB=1: C[n,m] = sum_k A[n,k]*B[m,k]   (score = qr @ keys^T)
// TRANSB=0: C[n,d] = sum_k A[n,k]*B[k,d]   (concat = s_memory @ keys)
template <int TRANSB>
__global__ void __launch_bounds__(256) k_sgemm(const float* __restrict__ A,
                                               const float* __restrict__ B,
                                               float* __restrict__ Cc) {
    __shared__ float As[16][132];
    __shared__ float Bs[16][132];
    const int tid = threadIdx.x;
    const int tx = tid & 15, ty = tid >> 4;
    const size_t row0 = (size_t)blockIdx.y * 128;
    const int col0 = blockIdx.x * 128;
    float acc[8][8] = {};

    for (int k0 = 0; k0 < 512; k0 += 16) {
        #pragma unroll
        for (int l = 0; l < 2; l++) {
            int lin = tid + l * 256;
            int r = lin >> 2;
            int kq = (lin & 3) * 4;
            float4 v = *(const float4*)&A[(row0 + r) * 512 + k0 + kq];
            As[kq + 0][r] = v.x; As[kq + 1][r] = v.y;
            As[kq + 2][r] = v.z; As[kq + 3][r] = v.w;
        }
        if (TRANSB) {
            #pragma unroll
            for (int l = 0; l < 2; l++) {
                int lin = tid + l * 256;
                int r = lin >> 2;
                int kq = (lin & 3) * 4;
                float4 v = *(const float4*)&B[(size_t)(col0 + r) * 512 + k0 + kq];
                Bs[kq + 0][r] = v.x; Bs[kq + 1][r] = v.y;
                Bs[kq + 2][r] = v.z; Bs[kq + 3][r] = v.w;
            }
        } else {
            #pragma unroll
            for (int l = 0; l < 2; l++) {
                int lin = tid + l * 256;
                int kk = lin >> 5;
                int c4 = (lin & 31) * 4;
                float4 v = *(const float4*)&B[(size_t)(k0 + kk) * 512 + col0 + c4];
                *(float4*)&Bs[kk][c4] = v;
            }
        }
        __syncthreads();
        #pragma unroll
        for (int k = 0; k < 16; k++) {
            float a[8], bb[8];
            *(float4*)&a[0]  = *(float4*)&As[k][ty * 8];
            *(float4*)&a[4]  = *(float4*)&As[k][ty * 8 + 4];
            *(float4*)&bb[0] = *(float4*)&Bs[k][tx * 8];
            *(float4*)&bb[4] = *(float4*)&Bs[k][tx * 8 + 4];
            #pragma unroll
            for (int i = 0; i < 8; i++)
                #pragma unroll
                for (int j = 0; j < 8; j++)
                    acc[i][j] += a[i] * bb[j];
        }
        __syncthreads();
    }
    #pragma unroll
    for (int i = 0; i < 8; i++) {
        size_t r = row0 + ty * 8 + i;
        #pragma unroll
        for (int j4 = 0; j4 < 2; j4++) {
            float4 v = make_float4(acc[i][j4 * 4 + 0], acc[i][j4 * 4 + 1],
                                   acc[i][j4 * 4 + 2], acc[i][j4 * 4 + 3]);
            *(float4*)&Cc[r * 512 + col0 + tx * 8 + j4 * 4] = v;
        }
    }
}

// ---------------- column softmax stats (axis=0) ----------------
__global__ void __launch_bounds__(512) k_colmax() {
    int m = threadIdx.x;
    size_t r0 = (size_t)blockIdx.x * 128;
    float mx = -FLT_MAX;
    for (int r = 0; r < 128; r++) mx = fmaxf(mx, g_score[(r0 + r) * 512 + m]);
    atomicMaxF(&g_cmax[m], mx);
}

__global__ void __launch_bounds__(512) k_colsum() {
    int m = threadIdx.x;
    float cm = g_cmax[m];
    size_t r0 = (size_t)blockIdx.x * 128;
    float s = 0.0f;
    for (int r = 0; r < 128; r++) s += expf(g_score[(r0 + r) * 512 + m] - cm);
    atomicAdd(&g_csum[m], s);
}

// ---------------- per-row pass: row softmax, s_query, top2, w, losses, counts ----------------
__global__ void __launch_bounds__(256) k_row(float* __restrict__ out_sq,
                                             float* __restrict__ out_sm,
                                             const float* __restrict__ keys) {
    __shared__ float cms[512];
    __shared__ float cssi[512];
    __shared__ double wcomp[8], wsep[8];
    for (int i = threadIdx.x; i < 512; i += 256) {
        cms[i] = g_cmax[i];
        cssi[i] = 1.0f / g_csum[i];
    }
    __syncthreads();
    int warp = threadIdx.x >> 5, lane = threadIdx.x & 31;
    size_t n = (size_t)blockIdx.x * 8 + warp;
    const float* srow = g_score + n * 512;
    float sc[16];
    #pragma unroll
    for (int t = 0; t < 16; t++) sc[t] = srow[lane + t * 32];

    // per-lane top2 then warp merge
    float v1 = -FLT_MAX, v2 = -FLT_MAX; int i1 = 0, i2 = 0;
    #pragma unroll
    for (int t = 0; t < 16; t++) {
        int c = lane + t * 32; float v = sc[t];
        if (v > v1) { v2 = v1; i2 = i1; v1 = v; i1 = c; }
        else if (v > v2) { v2 = v; i2 = c; }
    }
    #pragma unroll
    for (int off = 16; off; off >>= 1) {
        float ov1 = __shfl_down_sync(0xffffffffu, v1, off);
        int   oi1 = __shfl_down_sync(0xffffffffu, i1, off);
        float ov2 = __shfl_down_sync(0xffffffffu, v2, off);
        int   oi2 = __shfl_down_sync(0xffffffffu, i2, off);
        if (ov1 > v1) { v2 = v1; i2 = i1; v1 = ov1; i1 = oi1; if (ov2 > v2) { v2 = ov2; i2 = oi2; } }
        else if (ov1 > v2) { v2 = ov1; i2 = oi1; }
    }
    v1 = __shfl_sync(0xffffffffu, v1, 0);
    i1 = __shfl_sync(0xffffffffu, i1, 0);
    i2 = __shfl_sync(0xffffffffu, i2, 0);

    // row softmax (s_memory) and s_query
    float ex[16]; float rs = 0.0f;
    #pragma unroll
    for (int t = 0; t < 16; t++) { ex[t] = expf(sc[t] - v1); rs += ex[t]; }
    #pragma unroll
    for (int o = 16; o; o >>= 1) rs += __shfl_xor_sync(0xffffffffu, rs, o);
    float inv_rs = 1.0f / rs;
    float* smrow = out_sm + n * 512;
    float* sqrow = out_sq + n * 512;
    #pragma unroll
    for (int t = 0; t < 16; t++) {
        int c = lane + t * 32;
        smrow[c] = ex[t] * inv_rs;
        sqrow[c] = expf(sc[t] - cms[c]) * cssi[c];
    }
    if (lane == 0) {
        g_gi[n] = i1;
        g_w[n] = expf(v1 - cms[i1]);     // = s_query[n,gi] / colmax(s_query)[gi]
        atomicAdd(&g_count[i1], 1);
    }

    // losses
    const float* qrow = g_qr + n * 512;
    const float* pk = keys + (size_t)i1 * 512;
    const float* nk = keys + (size_t)i2 * 512;
    float comp = 0.0f, dp = 0.0f, dn = 0.0f;
    #pragma unroll
    for (int t = 0; t < 16; t++) {
        int c = lane + t * 32;
        float q = qrow[c], p = pk[c], gg = nk[c];
        float d0 = q - p; comp += d0 * d0;
        float d1 = d0 + 1e-6f; dp += d1 * d1;
        float d2 = (q - gg) + 1e-6f; dn += d2 * d2;
    }
    #pragma unroll
    for (int o = 16; o; o >>= 1) {
        comp += __shfl_xor_sync(0xffffffffu, comp, o);
        dp   += __shfl_xor_sync(0xffffffffu, dp, o);
        dn   += __shfl_xor_sync(0xffffffffu, dn, o);
    }
    if (lane == 0) {
        wcomp[warp] = (double)comp;
        wsep[warp] = (double)fmaxf(0.0f, sqrtf(dp) - sqrtf(dn) + 1.0f);
    }
    __syncthreads();
    if (threadIdx.x == 0) {
        double c = 0.0, s = 0.0;
        for (int wv = 0; wv < 8; wv++) { c += wcomp[wv]; s += wsep[wv]; }
        atomicAdd(&g_comp, c);
        atomicAdd(&g_sep, s);
    }
}

// ---------------- counting sort of rows by gi ----------------
__global__ void __launch_bounds__(512) k_scan() {
    __shared__ int s[512];
    int t = threadIdx.x;
    int v = g_count[t];
    s[t] = v;
    __syncthreads();
    for (int off = 1; off < 512; off <<= 1) {
        int add = (t >= off) ? s[t - off] : 0;
        __syncthreads();
        s[t] += add;
        __syncthreads();
    }
    g_offset[t + 1] = s[t];
    if (t == 0) g_offset[0] = 0;
    g_cursor[t] = s[t] - v;
}

__global__ void k_scatter() {
    for (int n = blockIdx.x * blockDim.x + threadIdx.x; n < NTOT; n += gridDim.x * blockDim.x) {
        int m = g_gi[n];
        int idx = atomicAdd(&g_cursor[m], 1);
        g_list[idx] = n;
    }
}

// ---------------- memory update: segment sum + l2norm ----------------
__global__ void __launch_bounds__(512) k_update(const float* __restrict__ keys,
                                                float* __restrict__ outUM) {
    int m = blockIdx.x;
    int t = threadIdx.x;
    __shared__ int sln[256];
    __shared__ float slw[256];
    __shared__ float red[16];
    __shared__ float rn_s;
    int beg = g_offset[m], end = g_offset[m + 1];
    float acc = 0.0f;
    for (int base = beg; base < end; base += 256) {
        int cnt = min(256, end - base);
        __syncthreads();
        if (t < cnt) { int n = g_list[base + t]; sln[t] = n; slw[t] = g_w[n]; }
        __syncthreads();
        for (int i = 0; i < cnt; i++)
            acc += slw[i] * g_qr[(size_t)sln[i] * 512 + t];
    }
    float um = acc + keys[(size_t)m * 512 + t];
    float ss = um * um;
    #pragma unroll
    for (int o = 16; o; o >>= 1) ss += __shfl_xor_sync(0xffffffffu, ss, o);
    if ((t & 31) == 0) red[t >> 5] = ss;
    __syncthreads();
    if (t == 0) {
        float x = 0.0f;
        for (int i = 0; i < 16; i++) x += red[i];
        rn_s = 1.0f / fmaxf(sqrtf(x), 1e-12f);
    }
    __syncthreads();
    outUM[(size_t)m * 512 + t] = um * rn_s;
}

// ---------------- transpose (N,512) -> (B, c, hw) into updated_query ----------------
__global__ void k_transpose(const float* __restrict__ src, float* __restrict__ out, int cOff) {
    __shared__ float t[32][33];
    int c0 = blockIdx.x * 32;
    int n0 = blockIdx.y * 32;
    int tx = threadIdx.x, ty = threadIdx.y;
    for (int r = ty; r < 32; r += 8)
        t[r][tx] = src[(size_t)(n0 + r) * 512 + c0 + tx];
    __syncthreads();
    int b = n0 >> 12;
    int hw0 = n0 & 4095;
    size_t obase = (size_t)b * 1024 * 4096 + (size_t)(cOff + c0) * 4096 + hw0;
    for (int r = ty; r < 32; r += 8)
        out[obase + (size_t)r * 4096 + tx] = t[tx][r];
}

// ---------------- losses ----------------
__global__ void k_finalize(float* __restrict__ out) {
    out[OFF_SEP] = (float)(g_sep / (double)NTOT);
    out[OFF_COMP] = (float)(g_comp / ((double)NTOT * (double)CDIM));
}

// ---------------- launch ----------------
extern "C" void kernel_launch(void* const* d_in, const int* in_sizes, int n_in,
                              void* d_out, int out_size) {
    const float* query = (const float*)d_in[0];
    const float* keys  = (const float*)d_in[1];
    float* out = (float*)d_out;

    float *p_qr = nullptr, *p_score = nullptr;
    cudaGetSymbolAddress((void**)&p_qr, g_qr);
    cudaGetSymbolAddress((void**)&p_score, g_score);

    k_init<<<2, 256>>>();
    k_normalize<<<NTOT / 16, 256>>>(query);
    k_sgemm<1><<<dim3(4, NTOT / 128), 256>>>(p_qr, keys, p_score);
    k_colmax<<<NTOT / 128, 512>>>();
    k_colsum<<<NTOT / 128, 512>>>();
    k_row<<<NTOT / 8, 256>>>(out + OFF_SQ, out + OFF_SM, keys);
    k_scan<<<1, 512>>>();
    k_scatter<<<64, 256>>>();
    k_update<<<MDIM, 512>>>(keys, out + OFF_UM);
    k_sgemm<0><<<dim3(4, NTOT / 128), 256>>>(out + OFF_SM, keys, p_score);
    k_transpose<<<dim3(16, NTOT / 32), dim3(32, 8)>>>(p_qr, out, 0);
    k_transpose<<<dim3(16, NTOT / 32), dim3(32, 8)>>>(p_score, out, 512);
    k_finalize<<<1, 1>>>(out);
}

// round 5
// speedup vs baseline: 1.8340x; 1.8340x over previous
#include <cuda_runtime.h>
#include <cuda_bf16.h>
#include <math.h>
#include <float.h>
#include <stdint.h>

// Problem constants
#define NTOT 65536          // B*H*W
#define CDIM 512            // channels / key dim
#define MDIM 512            // number of memory slots
#define HWDIM 4096          // H*W

// Output packing offsets (flat concat of the returned tuple, fp32)
#define OFF_UQ   0LL
#define OFF_UM   67108864LL           // 16*1024*4096
#define OFF_SQ   67371008LL           // + 512*512
#define OFF_SM   100925440LL          // + 65536*512
#define OFF_SEP  134479872LL          // + 65536*512
#define OFF_COMP 134479873LL

// ---------------- device scratch (no allocations allowed) ----------------
__device__ float  g_qr[(size_t)NTOT * CDIM];      // normalized query rows
__device__ float  g_score[(size_t)NTOT * MDIM];   // score, reused for concat_memory
__device__ float  g_keysT[(size_t)MDIM * CDIM];   // transposed keys for GEMM2
__device__ float  g_cmax[MDIM];
__device__ float  g_csum[MDIM];                   // unshifted sum exp(score) per column
__device__ float  g_w[NTOT];
__device__ int    g_gi[NTOT];
__device__ int    g_count[MDIM];
__device__ int    g_offset[MDIM + 1];
__device__ int    g_cursor[MDIM];
__device__ int    g_list[NTOT];
__device__ double g_comp, g_sep;

// ---------------- helpers ----------------
__device__ __forceinline__ void atomicMaxF(float* addr, float val) {
    int* ia = (int*)addr;
    int old = *ia;
    while (__int_as_float(old) < val) {
        int assumed = old;
        old = atomicCAS(ia, assumed, __float_as_int(val));
        if (old == assumed) break;
    }
}

// ======================= bf16 3x-split warp-MMA GEMM =======================
// C[i, col0+j] = sum_k A[i,k] * Bp[col0+j, k]   (both operands K-major fp32)
// CTA tile 128x128, K-chunk 32, double-buffered smem (2 x 32KB).
// Per k-chunk smem stage layout (byte offsets from stage base):
//   A_hi 0..8192 | A_lo 8192..16384 | B_hi 16384..24576 | B_lo 24576..32768
// Row layout: 64B per row (32 bf16), 4x16B chunks, chunk XOR-swizzled by (row>>1)&3.

__device__ __forceinline__ void ldm4(uint32_t* r, uint32_t a) {
    asm volatile("ldmatrix.sync.aligned.m8n8.x4.shared.b16 {%0,%1,%2,%3}, [%4];"
        : "=r"(r[0]), "=r"(r[1]), "=r"(r[2]), "=r"(r[3]) : "r"(a));
}
__device__ __forceinline__ void mma16816(float* d, const uint32_t* a, uint32_t b0, uint32_t b1) {
    asm volatile("mma.sync.aligned.m16n8k16.row.col.f32.bf16.bf16.f32 "
        "{%0,%1,%2,%3}, {%4,%5,%6,%7}, {%8,%9}, {%0,%1,%2,%3};"
        : "+f"(d[0]), "+f"(d[1]), "+f"(d[2]), "+f"(d[3])
        : "r"(a[0]), "r"(a[1]), "r"(a[2]), "r"(a[3]), "r"(b0), "r"(b1));
}

__device__ __forceinline__ void bsplit8(float4 v0, float4 v1, uint4& hi, uint4& lo) {
    float f[8] = {v0.x, v0.y, v0.z, v0.w, v1.x, v1.y, v1.z, v1.w};
    uint32_t h[4], l[4];
    #pragma unroll
    for (int i = 0; i < 4; i++) {
        __nv_bfloat16 h0 = __float2bfloat16(f[2*i]);
        __nv_bfloat16 h1 = __float2bfloat16(f[2*i+1]);
        float l0 = f[2*i]   - __bfloat162float(h0);
        float l1 = f[2*i+1] - __bfloat162float(h1);
        __nv_bfloat162 hp; hp.x = h0; hp.y = h1;
        __nv_bfloat162 lp; lp.x = __float2bfloat16(l0); lp.y = __float2bfloat16(l1);
        h[i] = *(uint32_t*)&hp;
        l[i] = *(uint32_t*)&lp;
    }
    hi = make_uint4(h[0], h[1], h[2], h[3]);
    lo = make_uint4(l[0], l[1], l[2], l[3]);
}

__device__ __forceinline__ void stage_load(const float* __restrict__ A,
                                           const float* __restrict__ Bp,
                                           size_t row0, int col0, char* st,
                                           int k0, int tid) {
    #pragma unroll
    for (int it = 0; it < 2; it++) {
        int slot = tid + it * 256;
        int r = slot >> 2, c = slot & 3;
        const float* p = A + (row0 + r) * 512 + k0 + c * 8;
        float4 v0 = *(const float4*)p;
        float4 v1 = *(const float4*)(p + 4);
        uint4 hi, lo; bsplit8(v0, v1, hi, lo);
        int off = r * 64 + ((c ^ ((r >> 1) & 3)) << 4);
        *(uint4*)(st + off)        = hi;
        *(uint4*)(st + 8192 + off) = lo;
    }
    #pragma unroll
    for (int it = 0; it < 2; it++) {
        int slot = tid + it * 256;
        int r = slot >> 2, c = slot & 3;
        const float* p = Bp + (size_t)(col0 + r) * 512 + k0 + c * 8;
        float4 v0 = *(const float4*)p;
        float4 v1 = *(const float4*)(p + 4);
        uint4 hi, lo; bsplit8(v0, v1, hi, lo);
        int off = r * 64 + ((c ^ ((r >> 1) & 3)) << 4);
        *(uint4*)(st + 16384 + off) = hi;
        *(uint4*)(st + 24576 + off) = lo;
    }
}

__global__ void __launch_bounds__(256, 2) k_mma(const float* __restrict__ A,
                                                const float* __restrict__ Bp,
                                                float* __restrict__ C) {
    extern __shared__ char sm[];
    const int tid = threadIdx.x, lane = tid & 31, wid = tid >> 5;
    const size_t row0 = (size_t)blockIdx.y * 128;
    const int col0 = blockIdx.x * 128;
    const int warp_i = (wid & 3) * 32;      // 4 warps along i
    const int warp_j = (wid >> 2) * 64;     // 2 warps along j

    float acc[2][8][4];
    #pragma unroll
    for (int a = 0; a < 2; a++)
        #pragma unroll
        for (int b = 0; b < 8; b++)
            #pragma unroll
            for (int c = 0; c < 4; c++) acc[a][b][c] = 0.0f;

    // per-lane ldmatrix addressing
    const int lrow = (lane & 7) + ((lane >> 3) & 1) * 8;   // 0..15 within tile
    const int lsel = lane >> 4;                             // +0/+1 chunk select
    const int arow = warp_i + lrow;
    const int asw  = (arow >> 1) & 3;
    const int brow = warp_j + lrow;
    const int bsw  = (brow >> 1) & 3;
    const uint32_t smb = (uint32_t)__cvta_generic_to_shared(sm);

    stage_load(A, Bp, row0, col0, sm, 0, tid);
    __syncthreads();

    for (int ch = 0; ch < 16; ch++) {
        int s = ch & 1;
        uint32_t stb = smb + (uint32_t)s * 32768u;
        if (ch < 15)
            stage_load(A, Bp, row0, col0, sm + (s ^ 1) * 32768, (ch + 1) * 32, tid);
        #pragma unroll
        for (int ks = 0; ks < 2; ks++) {
            int cidx = ks * 2 + lsel;
            uint32_t ah[2][4], al[2][4], bb[4][4];
            #pragma unroll
            for (int fi = 0; fi < 2; fi++) {
                uint32_t ad = stb + (uint32_t)((arow + fi * 16) * 64 + ((cidx ^ asw) << 4));
                ldm4(ah[fi], ad);
                ldm4(al[fi], ad + 8192u);
            }
            #pragma unroll
            for (int g = 0; g < 4; g++) {
                uint32_t bd = stb + 16384u + (uint32_t)((brow + g * 16) * 64 + ((cidx ^ bsw) << 4));
                ldm4(bb[g], bd);
            }
            #pragma unroll
            for (int fi = 0; fi < 2; fi++)
                #pragma unroll
                for (int g = 0; g < 4; g++) {
                    mma16816(acc[fi][2*g],   ah[fi], bb[g][0], bb[g][2]);
                    mma16816(acc[fi][2*g+1], ah[fi], bb[g][1], bb[g][3]);
                    mma16816(acc[fi][2*g],   al[fi], bb[g][0], bb[g][2]);
                    mma16816(acc[fi][2*g+1], al[fi], bb[g][1], bb[g][3]);
                }
            #pragma unroll
            for (int g = 0; g < 4; g++) {
                uint32_t bd = stb + 24576u + (uint32_t)((brow + g * 16) * 64 + ((cidx ^ bsw) << 4));
                ldm4(bb[g], bd);
            }
            #pragma unroll
            for (int fi = 0; fi < 2; fi++)
                #pragma unroll
                for (int g = 0; g < 4; g++) {
                    mma16816(acc[fi][2*g],   ah[fi], bb[g][0], bb[g][2]);
                    mma16816(acc[fi][2*g+1], ah[fi], bb[g][1], bb[g][3]);
                }
        }
        __syncthreads();
    }

    // epilogue: d0,d1 -> (row, col..col+1); d2,d3 -> (row+8, ...)
    #pragma unroll
    for (int fi = 0; fi < 2; fi++) {
        size_t r = row0 + warp_i + fi * 16 + (lane >> 2);
        #pragma unroll
        for (int fj = 0; fj < 8; fj++) {
            int cc = col0 + warp_j + fj * 8 + (lane & 3) * 2;
            *(float2*)&C[r * 512 + cc]       = make_float2(acc[fi][fj][0], acc[fi][fj][1]);
            *(float2*)&C[(r + 8) * 512 + cc] = make_float2(acc[fi][fj][2], acc[fi][fj][3]);
        }
    }
}

// ---------------- keys transpose (for GEMM2 K-major B) ----------------
__global__ void k_tkeys(const float* __restrict__ keys) {
    __shared__ float t[32][33];
    int c0 = blockIdx.x * 32;
    int r0 = blockIdx.y * 32;
    int tx = threadIdx.x, ty = threadIdx.y;
    for (int r = ty; r < 32; r += 8)
        t[r][tx] = keys[(size_t)(r0 + r) * 512 + c0 + tx];
    __syncthreads();
    for (int r = ty; r < 32; r += 8)
        g_keysT[(size_t)(c0 + r) * 512 + r0 + tx] = t[tx][r];
}

// ---------------- init ----------------
__global__ void k_init() {
    int t = blockIdx.x * blockDim.x + threadIdx.x;
    if (t < MDIM) { g_cmax[t] = -FLT_MAX; g_csum[t] = 0.0f; g_count[t] = 0; }
    if (t == 0) { g_comp = 0.0; g_sep = 0.0; }
}

// ---------------- L2 normalize over channels + transpose to (N, C) ----------------
__global__ void __launch_bounds__(256) k_normalize(const float* __restrict__ query) {
    __shared__ float s[CDIM * 17];
    __shared__ float psum[256];
    __shared__ float rn[16];
    int p0 = blockIdx.x * 16;
    int b = p0 >> 12;
    int hw0 = p0 & 4095;
    const float* qb = query + (size_t)b * CDIM * HWDIM + hw0;
    int tid = threadIdx.x;
    #pragma unroll
    for (int it = 0; it < 32; it++) {
        int i = it * 256 + tid;
        int c = i >> 4, j = i & 15;
        s[c * 17 + j] = qb[(size_t)c * HWDIM + j];
    }
    __syncthreads();
    {
        int j = tid & 15, g = tid >> 4;
        float acc = 0.0f;
        #pragma unroll
        for (int cc = 0; cc < 32; cc++) {
            float v = s[(g * 32 + cc) * 17 + j];
            acc += v * v;
        }
        psum[tid] = acc;
    }
    __syncthreads();
    if (tid < 16) {
        float tot = 0.0f;
        #pragma unroll
        for (int g = 0; g < 16; g++) tot += psum[g * 16 + tid];
        rn[tid] = 1.0f / fmaxf(sqrtf(tot), 1e-12f);
    }
    __syncthreads();
    #pragma unroll
    for (int it = 0; it < 32; it++) {
        int i = it * 256 + tid;
        int c = i & 511, j = i >> 9;
        g_qr[(size_t)(p0 + j) * CDIM + c] = s[c * 17 + j] * rn[j];
    }
}

// ---------------- fused column stats: max + unshifted sum(exp) ----------------
__global__ void __launch_bounds__(512) k_colstat() {
    int m = threadIdx.x;
    size_t r0 = (size_t)blockIdx.x * 128;
    float mx = -FLT_MAX, sm = 0.0f;
    for (int r = 0; r < 128; r++) {
        float v = g_score[(r0 + r) * 512 + m];
        mx = fmaxf(mx, v);
        sm += expf(v);        // |score| <= ~23 -> no overflow without shift
    }
    atomicMaxF(&g_cmax[m], mx);
    atomicAdd(&g_csum[m], sm);
}

// ---------------- per-row pass: row softmax, s_query, top2, w, losses, counts ----------------
__global__ void __launch_bounds__(256) k_row(float* __restrict__ out_sq,
                                             float* __restrict__ out_sm,
                                             const float* __restrict__ keys) {
    __shared__ float cms[512];
    __shared__ float cssi[512];
    __shared__ double wcomp[8], wsep[8];
    for (int i = threadIdx.x; i < 512; i += 256) {
        float cm = g_cmax[i];
        cms[i] = cm;
        cssi[i] = 1.0f / (g_csum[i] * expf(-cm));   // = 1 / sum exp(score - cmax)
    }
    __syncthreads();
    int warp = threadIdx.x >> 5, lane = threadIdx.x & 31;
    size_t n = (size_t)blockIdx.x * 8 + warp;
    const float* srow = g_score + n * 512;
    float sc[16];
    #pragma unroll
    for (int t = 0; t < 16; t++) sc[t] = srow[lane + t * 32];

    float v1 = -FLT_MAX, v2 = -FLT_MAX; int i1 = 0, i2 = 0;
    #pragma unroll
    for (int t = 0; t < 16; t++) {
        int c = lane + t * 32; float v = sc[t];
        if (v > v1) { v2 = v1; i2 = i1; v1 = v; i1 = c; }
        else if (v > v2) { v2 = v; i2 = c; }
    }
    #pragma unroll
    for (int off = 16; off; off >>= 1) {
        float ov1 = __shfl_down_sync(0xffffffffu, v1, off);
        int   oi1 = __shfl_down_sync(0xffffffffu, i1, off);
        float ov2 = __shfl_down_sync(0xffffffffu, v2, off);
        int   oi2 = __shfl_down_sync(0xffffffffu, i2, off);
        if (ov1 > v1) { v2 = v1; i2 = i1; v1 = ov1; i1 = oi1; if (ov2 > v2) { v2 = ov2; i2 = oi2; } }
        else if (ov1 > v2) { v2 = ov1; i2 = oi1; }
    }
    v1 = __shfl_sync(0xffffffffu, v1, 0);
    i1 = __shfl_sync(0xffffffffu, i1, 0);
    i2 = __shfl_sync(0xffffffffu, i2, 0);

    float ex[16]; float rs = 0.0f;
    #pragma unroll
    for (int t = 0; t < 16; t++) { ex[t] = expf(sc[t] - v1); rs += ex[t]; }
    #pragma unroll
    for (int o = 16; o; o >>= 1) rs += __shfl_xor_sync(0xffffffffu, rs, o);
    float inv_rs = 1.0f / rs;
    float* smrow = out_sm + n * 512;
    float* sqrow = out_sq + n * 512;
    #pragma unroll
    for (int t = 0; t < 16; t++) {
        int c = lane + t * 32;
        smrow[c] = ex[t] * inv_rs;
        sqrow[c] = expf(sc[t] - cms[c]) * cssi[c];
    }
    if (lane == 0) {
        g_gi[n] = i1;
        g_w[n] = expf(v1 - cms[i1]);
        atomicAdd(&g_count[i1], 1);
    }

    const float* qrow = g_qr + n * 512;
    const float* pk = keys + (size_t)i1 * 512;
    const float* nk = keys + (size_t)i2 * 512;
    float comp = 0.0f, dp = 0.0f, dn = 0.0f;
    #pragma unroll
    for (int t = 0; t < 16; t++) {
        int c = lane + t * 32;
        float q = qrow[c], p = pk[c], gg = nk[c];
        float d0 = q - p; comp += d0 * d0;
        float d1 = d0 + 1e-6f; dp += d1 * d1;
        float d2 = (q - gg) + 1e-6f; dn += d2 * d2;
    }
    #pragma unroll
    for (int o = 16; o; o >>= 1) {
        comp += __shfl_xor_sync(0xffffffffu, comp, o);
        dp   += __shfl_xor_sync(0xffffffffu, dp, o);
        dn   += __shfl_xor_sync(0xffffffffu, dn, o);
    }
    if (lane == 0) {
        wcomp[warp] = (double)comp;
        wsep[warp] = (double)fmaxf(0.0f, sqrtf(dp) - sqrtf(dn) + 1.0f);
    }
    __syncthreads();
    if (threadIdx.x == 0) {
        double c = 0.0, s = 0.0;
        for (int wv = 0; wv < 8; wv++) { c += wcomp[wv]; s += wsep[wv]; }
        atomicAdd(&g_comp, c);
        atomicAdd(&g_sep, s);
    }
}

// ---------------- counting sort of rows by gi ----------------
__global__ void __launch_bounds__(512) k_scan() {
    __shared__ int s[512];
    int t = threadIdx.x;
    int v = g_count[t];
    s[t] = v;
    __syncthreads();
    for (int off = 1; off < 512; off <<= 1) {
        int add = (t >= off) ? s[t - off] : 0;
        __syncthreads();
        s[t] += add;
        __syncthreads();
    }
    g_offset[t + 1] = s[t];
    if (t == 0) g_offset[0] = 0;
    g_cursor[t] = s[t] - v;
}

__global__ void k_scatter() {
    for (int n = blockIdx.x * blockDim.x + threadIdx.x; n < NTOT; n += gridDim.x * blockDim.x) {
        int m = g_gi[n];
        int idx = atomicAdd(&g_cursor[m], 1);
        g_list[idx] = n;
    }
}

// ---------------- memory update: segment sum + l2norm ----------------
__global__ void __launch_bounds__(512) k_update(const float* __restrict__ keys,
                                                float* __restrict__ outUM) {
    int m = blockIdx.x;
    int t = threadIdx.x;
    __shared__ int sln[256];
    __shared__ float slw[256];
    __shared__ float red[16];
    __shared__ float rn_s;
    int beg = g_offset[m], end = g_offset[m + 1];
    float acc = 0.0f;
    for (int base = beg; base < end; base += 256) {
        int cnt = min(256, end - base);
        __syncthreads();
        if (t < cnt) { int n = g_list[base + t]; sln[t] = n; slw[t] = g_w[n]; }
        __syncthreads();
        for (int i = 0; i < cnt; i++)
            acc += slw[i] * g_qr[(size_t)sln[i] * 512 + t];
    }
    float um = acc + keys[(size_t)m * 512 + t];
    float ss = um * um;
    #pragma unroll
    for (int o = 16; o; o >>= 1) ss += __shfl_xor_sync(0xffffffffu, ss, o);
    if ((t & 31) == 0) red[t >> 5] = ss;
    __syncthreads();
    if (t == 0) {
        float x = 0.0f;
        for (int i = 0; i < 16; i++) x += red[i];
        rn_s = 1.0f / fmaxf(sqrtf(x), 1e-12f);
    }
    __syncthreads();
    outUM[(size_t)m * 512 + t] = um * rn_s;
}

// ---------------- transpose (N,512) -> (B, c, hw) into updated_query ----------------
__global__ void k_transpose(const float* __restrict__ src, float* __restrict__ out, int cOff) {
    __shared__ float t[32][33];
    int c0 = blockIdx.x * 32;
    int n0 = blockIdx.y * 32;
    int tx = threadIdx.x, ty = threadIdx.y;
    for (int r = ty; r < 32; r += 8)
        t[r][tx] = src[(size_t)(n0 + r) * 512 + c0 + tx];
    __syncthreads();
    int b = n0 >> 12;
    int hw0 = n0 & 4095;
    size_t obase = (size_t)b * 1024 * 4096 + (size_t)(cOff + c0) * 4096 + hw0;
    for (int r = ty; r < 32; r += 8)
        out[obase + (size_t)r * 4096 + tx] = t[tx][r];
}

// ---------------- losses ----------------
__global__ void k_finalize(float* __restrict__ out) {
    out[OFF_SEP] = (float)(g_sep / (double)NTOT);
    out[OFF_COMP] = (float)(g_comp / ((double)NTOT * (double)CDIM));
}

// ---------------- launch ----------------
extern "C" void kernel_launch(void* const* d_in, const int* in_sizes, int n_in,
                              void* d_out, int out_size) {
    const float* query = (const float*)d_in[0];
    const float* keys  = (const float*)d_in[1];
    float* out = (float*)d_out;

    float *p_qr = nullptr, *p_score = nullptr, *p_keysT = nullptr;
    cudaGetSymbolAddress((void**)&p_qr, g_qr);
    cudaGetSymbolAddress((void**)&p_score, g_score);
    cudaGetSymbolAddress((void**)&p_keysT, g_keysT);

    cudaFuncSetAttribute(k_mma, cudaFuncAttributeMaxDynamicSharedMemorySize, 65536);

    k_init<<<2, 256>>>();
    k_normalize<<<NTOT / 16, 256>>>(query);
    k_tkeys<<<dim3(16, 16), dim3(32, 8)>>>(keys);
    k_mma<<<dim3(4, NTOT / 128), 256, 65536>>>(p_qr, keys, p_score);
    k_colstat<<<NTOT / 128, 512>>>();
    k_row<<<NTOT / 8, 256>>>(out + OFF_SQ, out + OFF_SM, keys);
    k_scan<<<1, 512>>>();
    k_scatter<<<64, 256>>>();
    k_update<<<MDIM, 512>>>(keys, out + OFF_UM);
    k_mma<<<dim3(4, NTOT / 128), 256, 65536>>>(out + OFF_SM, p_keysT, p_score);
    k_transpose<<<dim3(16, NTOT / 32), dim3(32, 8)>>>(p_qr, out, 0);
    k_transpose<<<dim3(16, NTOT / 32), dim3(32, 8)>>>(p_score, out, 512);
    k_finalize<<<1, 1>>>(out);
}

// round 6
// speedup vs baseline: 2.2144x; 1.2074x over previous
#include <cuda_runtime.h>
#include <cuda_bf16.h>
#include <math.h>
#include <float.h>
#include <stdint.h>

// Problem constants
#define NTOT 65536          // B*H*W
#define CDIM 512            // channels / key dim
#define MDIM 512            // number of memory slots
#define HWDIM 4096          // H*W

// Output packing offsets (flat concat of the returned tuple, fp32)
#define OFF_UQ   0LL
#define OFF_UM   67108864LL           // 16*1024*4096
#define OFF_SQ   67371008LL           // + 512*512
#define OFF_SM   100925440LL          // + 65536*512
#define OFF_SEP  134479872LL          // + 65536*512
#define OFF_COMP 134479873LL

// ---------------- device scratch (no allocations allowed) ----------------
__device__ float          g_qr[(size_t)NTOT * CDIM];     // normalized query rows (fp32)
__device__ float          g_score[(size_t)NTOT * MDIM];  // score matrix
__device__ __nv_bfloat16  g_Ah[(size_t)NTOT * CDIM];     // hi split of A (qr, then s_memory)
__device__ __nv_bfloat16  g_Al[(size_t)NTOT * CDIM];     // lo split
__device__ __nv_bfloat16  g_Bh[(size_t)MDIM * CDIM];     // keys hi
__device__ __nv_bfloat16  g_Bl[(size_t)MDIM * CDIM];     // keys lo
__device__ __nv_bfloat16  g_BTh[(size_t)CDIM * MDIM];    // keysT hi
__device__ __nv_bfloat16  g_BTl[(size_t)CDIM * MDIM];    // keysT lo
__device__ float  g_cmax[MDIM];
__device__ float  g_csum[MDIM];                   // unshifted sum exp(score) per column
__device__ float  g_w[NTOT];
__device__ int    g_gi[NTOT];
__device__ int    g_count[MDIM];
__device__ int    g_offset[MDIM + 1];
__device__ int    g_cursor[MDIM];
__device__ int    g_list[NTOT];
__device__ double g_comp, g_sep;

// ---------------- helpers ----------------
__device__ __forceinline__ void atomicMaxF(float* addr, float val) {
    int* ia = (int*)addr;
    int old = *ia;
    while (__int_as_float(old) < val) {
        int assumed = old;
        old = atomicCAS(ia, assumed, __float_as_int(val));
        if (old == assumed) break;
    }
}
__device__ __forceinline__ void bf16split(float v, __nv_bfloat16& h, __nv_bfloat16& l) {
    h = __float2bfloat16(v);
    l = __float2bfloat16(v - __bfloat162float(h));
}

// ======================= bf16 3x-split warp-MMA GEMM =======================
// C[i, col0+j] = sum_k A[i,k] * B[col0+j, k]  with pre-split bf16 operands.
// CTA tile 128x128, K-chunk 32, double-buffered smem (2 x 32KB), cp.async staging.
// Stage layout (bytes): Ah 0..8K | Al 8K..16K | Bh 16K..24K | Bl 24K..32K
// Row = 64B (32 bf16), 4x16B chunks, chunk XOR-swizzled by (row>>1)&3.

__device__ __forceinline__ void ldm4(uint32_t* r, uint32_t a) {
    asm volatile("ldmatrix.sync.aligned.m8n8.x4.shared.b16 {%0,%1,%2,%3}, [%4];"
        : "=r"(r[0]), "=r"(r[1]), "=r"(r[2]), "=r"(r[3]) : "r"(a));
}
__device__ __forceinline__ void mma16816(float* d, const uint32_t* a, uint32_t b0, uint32_t b1) {
    asm volatile("mma.sync.aligned.m16n8k16.row.col.f32.bf16.bf16.f32 "
        "{%0,%1,%2,%3}, {%4,%5,%6,%7}, {%8,%9}, {%0,%1,%2,%3};"
        : "+f"(d[0]), "+f"(d[1]), "+f"(d[2]), "+f"(d[3])
        : "r"(a[0]), "r"(a[1]), "r"(a[2]), "r"(a[3]), "r"(b0), "r"(b1));
}
__device__ __forceinline__ void cpa16(uint32_t dst, const void* src) {
    asm volatile("cp.async.cg.shared.global [%0], [%1], 16;" :: "r"(dst), "l"(src));
}

__device__ __forceinline__ void stage_cp(const __nv_bfloat16* __restrict__ Ah,
                                         const __nv_bfloat16* __restrict__ Al,
                                         const __nv_bfloat16* __restrict__ Bh,
                                         const __nv_bfloat16* __restrict__ Bl,
                                         size_t row0, int col0, uint32_t stb,
                                         int k0, int tid) {
    #pragma unroll
    for (int it = 0; it < 8; it++) {
        int o = tid + it * 256;
        int region = o >> 9;               // 0:Ah 1:Al 2:Bh 3:Bl (constant per it)
        int r = (o >> 2) & 127;
        int c = o & 3;
        uint32_t dst = stb + (uint32_t)(region * 8192 + r * 64 + ((c ^ ((r >> 1) & 3)) << 4));
        const __nv_bfloat16* src;
        if (region == 0)      src = Ah + (row0 + r) * 512 + k0 + c * 8;
        else if (region == 1) src = Al + (row0 + r) * 512 + k0 + c * 8;
        else if (region == 2) src = Bh + (size_t)(col0 + r) * 512 + k0 + c * 8;
        else                  src = Bl + (size_t)(col0 + r) * 512 + k0 + c * 8;
        cpa16(dst, src);
    }
}

// EPI=0: write C rows to Cout (row-major N x 512).
// EPI=1: write transposed into output: Cout[b*1024*4096 + (512+col0+d)*4096 + hw]
template <int EPI>
__global__ void __launch_bounds__(256, 2) k_mma(const __nv_bfloat16* __restrict__ Ah,
                                                const __nv_bfloat16* __restrict__ Al,
                                                const __nv_bfloat16* __restrict__ Bh,
                                                const __nv_bfloat16* __restrict__ Bl,
                                                float* __restrict__ Cout) {
    extern __shared__ char sm[];
    const int tid = threadIdx.x, lane = tid & 31, wid = tid >> 5;
    const size_t row0 = (size_t)blockIdx.y * 128;
    const int col0 = blockIdx.x * 128;
    const int warp_i = (wid & 3) * 32;      // 4 warps along i
    const int warp_j = (wid >> 2) * 64;     // 2 warps along j

    float acc[2][8][4];
    #pragma unroll
    for (int a = 0; a < 2; a++)
        #pragma unroll
        for (int b = 0; b < 8; b++)
            #pragma unroll
            for (int c = 0; c < 4; c++) acc[a][b][c] = 0.0f;

    const int lrow = (lane & 7) + ((lane >> 3) & 1) * 8;
    const int lsel = lane >> 4;
    const int arow = warp_i + lrow;
    const int asw  = (arow >> 1) & 3;
    const int brow = warp_j + lrow;
    const int bsw  = (brow >> 1) & 3;
    const uint32_t smb = (uint32_t)__cvta_generic_to_shared(sm);

    stage_cp(Ah, Al, Bh, Bl, row0, col0, smb, 0, tid);
    asm volatile("cp.async.commit_group;");

    for (int ch = 0; ch < 16; ch++) {
        int s = ch & 1;
        uint32_t stb = smb + (uint32_t)s * 32768u;
        if (ch < 15) {
            stage_cp(Ah, Al, Bh, Bl, row0, col0, smb + (uint32_t)(s ^ 1) * 32768u,
                     (ch + 1) * 32, tid);
            asm volatile("cp.async.commit_group;");
            asm volatile("cp.async.wait_group 1;");
        } else {
            asm volatile("cp.async.wait_group 0;");
        }
        __syncthreads();
        #pragma unroll
        for (int ks = 0; ks < 2; ks++) {
            int cidx = ks * 2 + lsel;
            uint32_t ah[2][4], al[2][4], bb[4][4];
            #pragma unroll
            for (int fi = 0; fi < 2; fi++) {
                uint32_t ad = stb + (uint32_t)((arow + fi * 16) * 64 + ((cidx ^ asw) << 4));
                ldm4(ah[fi], ad);
                ldm4(al[fi], ad + 8192u);
            }
            #pragma unroll
            for (int g = 0; g < 4; g++) {
                uint32_t bd = stb + 16384u + (uint32_t)((brow + g * 16) * 64 + ((cidx ^ bsw) << 4));
                ldm4(bb[g], bd);
            }
            #pragma unroll
            for (int fi = 0; fi < 2; fi++)
                #pragma unroll
                for (int g = 0; g < 4; g++) {
                    mma16816(acc[fi][2*g],   ah[fi], bb[g][0], bb[g][2]);
                    mma16816(acc[fi][2*g+1], ah[fi], bb[g][1], bb[g][3]);
                    mma16816(acc[fi][2*g],   al[fi], bb[g][0], bb[g][2]);
                    mma16816(acc[fi][2*g+1], al[fi], bb[g][1], bb[g][3]);
                }
            #pragma unroll
            for (int g = 0; g < 4; g++) {
                uint32_t bd = stb + 24576u + (uint32_t)((brow + g * 16) * 64 + ((cidx ^ bsw) << 4));
                ldm4(bb[g], bd);
            }
            #pragma unroll
            for (int fi = 0; fi < 2; fi++)
                #pragma unroll
                for (int g = 0; g < 4; g++) {
                    mma16816(acc[fi][2*g],   ah[fi], bb[g][0], bb[g][2]);
                    mma16816(acc[fi][2*g+1], ah[fi], bb[g][1], bb[g][3]);
                }
        }
        __syncthreads();
    }

    if (EPI == 0) {
        // plain row-major write
        #pragma unroll
        for (int fi = 0; fi < 2; fi++) {
            size_t r = row0 + warp_i + fi * 16 + (lane >> 2);
            #pragma unroll
            for (int fj = 0; fj < 8; fj++) {
                int cc = col0 + warp_j + fj * 8 + (lane & 3) * 2;
                *(float2*)&Cout[r * 512 + cc]       = make_float2(acc[fi][fj][0], acc[fi][fj][1]);
                *(float2*)&Cout[(r + 8) * 512 + cc] = make_float2(acc[fi][fj][2], acc[fi][fj][3]);
            }
        }
    } else {
        // transposed write via smem tile (two 64-row halves), stride 129 (conflict-free)
        float* tile = (float*)sm;
        size_t b = row0 >> 12;
        int hwb = (int)(row0 & 4095);
        float* obase = Cout + b * (1024LL * 4096LL) + (size_t)(512 + col0) * 4096;
        #pragma unroll
        for (int h = 0; h < 2; h++) {
            if (((wid & 3) >> 1) == h) {
                int rbase = warp_i - h * 64;    // 0 or 32
                #pragma unroll
                for (int fi = 0; fi < 2; fi++) {
                    int rr = rbase + fi * 16 + (lane >> 2);
                    #pragma unroll
                    for (int fj = 0; fj < 8; fj++) {
                        int cc = warp_j + fj * 8 + (lane & 3) * 2;
                        tile[rr * 129 + cc]           = acc[fi][fj][0];
                        tile[rr * 129 + cc + 1]       = acc[fi][fj][1];
                        tile[(rr + 8) * 129 + cc]     = acc[fi][fj][2];
                        tile[(rr + 8) * 129 + cc + 1] = acc[fi][fj][3];
                    }
                }
            }
            __syncthreads();
            int hw0 = hwb + h * 64;
            #pragma unroll
            for (int it = 0; it < 16; it++) {
                int d = wid * 16 + it;
                float v0 = tile[lane * 129 + d];
                float v1 = tile[(lane + 32) * 129 + d];
                obase[(size_t)d * 4096 + hw0 + lane]      = v0;
                obase[(size_t)d * 4096 + hw0 + 32 + lane] = v1;
            }
            __syncthreads();
        }
    }
}

// ---------------- keys prep: splits of keys and keys^T ----------------
__global__ void k_prepkeys(const float* __restrict__ keys) {
    __shared__ float t[32][33];
    int c0 = blockIdx.x * 32;
    int r0 = blockIdx.y * 32;
    int tx = threadIdx.x, ty = threadIdx.y;
    for (int r = ty; r < 32; r += 8) {
        float v = keys[(size_t)(r0 + r) * 512 + c0 + tx];
        t[r][tx] = v;
        __nv_bfloat16 h, l; bf16split(v, h, l);
        g_Bh[(size_t)(r0 + r) * 512 + c0 + tx] = h;
        g_Bl[(size_t)(r0 + r) * 512 + c0 + tx] = l;
    }
    __syncthreads();
    for (int r = ty; r < 32; r += 8) {
        float v = t[tx][r];
        __nv_bfloat16 h, l; bf16split(v, h, l);
        g_BTh[(size_t)(c0 + r) * 512 + r0 + tx] = h;
        g_BTl[(size_t)(c0 + r) * 512 + r0 + tx] = l;
    }
}

// ---------------- init ----------------
__global__ void k_init() {
    int t = blockIdx.x * blockDim.x + threadIdx.x;
    if (t < MDIM) { g_cmax[t] = -FLT_MAX; g_csum[t] = 0.0f; g_count[t] = 0; }
    if (t == 0) { g_comp = 0.0; g_sep = 0.0; }
}

// ---------------- L2 normalize + transpose to (N,C) + bf16 split + direct UQ output ----------------
__global__ void __launch_bounds__(256) k_normalize(const float* __restrict__ query,
                                                   float* __restrict__ out) {
    __shared__ float s[CDIM * 17];
    __shared__ float psum[256];
    __shared__ float rn[16];
    int p0 = blockIdx.x * 16;
    int b = p0 >> 12;
    int hw0 = p0 & 4095;
    const float* qb = query + (size_t)b * CDIM * HWDIM + hw0;
    int tid = threadIdx.x;
    #pragma unroll
    for (int it = 0; it < 32; it++) {
        int i = it * 256 + tid;
        int c = i >> 4, j = i & 15;
        s[c * 17 + j] = qb[(size_t)c * HWDIM + j];
    }
    __syncthreads();
    {
        int j = tid & 15, g = tid >> 4;
        float acc = 0.0f;
        #pragma unroll
        for (int cc = 0; cc < 32; cc++) {
            float v = s[(g * 32 + cc) * 17 + j];
            acc += v * v;
        }
        psum[tid] = acc;
    }
    __syncthreads();
    if (tid < 16) {
        float tot = 0.0f;
        #pragma unroll
        for (int g = 0; g < 16; g++) tot += psum[g * 16 + tid];
        rn[tid] = 1.0f / fmaxf(sqrtf(tot), 1e-12f);
    }
    __syncthreads();
    // (N,C) fp32 + bf16 splits
    #pragma unroll
    for (int it = 0; it < 32; it++) {
        int i = it * 256 + tid;
        int c = i & 511, j = i >> 9;
        float v = s[c * 17 + j] * rn[j];
        size_t idx = (size_t)(p0 + j) * CDIM + c;
        g_qr[idx] = v;
        __nv_bfloat16 h, l; bf16split(v, h, l);
        g_Ah[idx] = h;
        g_Al[idx] = l;
    }
    // direct transposed output: updated_query[:, 0:512] = qr in (B,C,HW)
    float* ob = out + (size_t)b * (1024LL * 4096LL) + hw0;
    #pragma unroll
    for (int it = 0; it < 32; it++) {
        int i = it * 256 + tid;
        int c = i >> 4, j = i & 15;
        ob[(size_t)c * 4096 + j] = s[c * 17 + j] * rn[j];
    }
}

// ---------------- fused column stats: max + unshifted sum(exp) ----------------
__global__ void __launch_bounds__(512) k_colstat() {
    int m = threadIdx.x;
    size_t r0 = (size_t)blockIdx.x * 128;
    float mx = -FLT_MAX, sm = 0.0f;
    for (int r = 0; r < 128; r++) {
        float v = g_score[(r0 + r) * 512 + m];
        mx = fmaxf(mx, v);
        sm += expf(v);
    }
    atomicMaxF(&g_cmax[m], mx);
    atomicAdd(&g_csum[m], sm);
}

// ---------------- per-row pass: softmaxes, top2, w, losses, counts + sm splits ----------------
__global__ void __launch_bounds__(256) k_row(float* __restrict__ out_sq,
                                             float* __restrict__ out_sm,
                                             const float* __restrict__ keys) {
    __shared__ float cms[512];
    __shared__ float cssi[512];
    __shared__ double wcomp[8], wsep[8];
    for (int i = threadIdx.x; i < 512; i += 256) {
        float cm = g_cmax[i];
        cms[i] = cm;
        cssi[i] = 1.0f / (g_csum[i] * expf(-cm));
    }
    __syncthreads();
    int warp = threadIdx.x >> 5, lane = threadIdx.x & 31;
    size_t n = (size_t)blockIdx.x * 8 + warp;
    const float* srow = g_score + n * 512;
    float sc[16];
    #pragma unroll
    for (int t = 0; t < 16; t++) sc[t] = srow[lane + t * 32];

    float v1 = -FLT_MAX, v2 = -FLT_MAX; int i1 = 0, i2 = 0;
    #pragma unroll
    for (int t = 0; t < 16; t++) {
        int c = lane + t * 32; float v = sc[t];
        if (v > v1) { v2 = v1; i2 = i1; v1 = v; i1 = c; }
        else if (v > v2) { v2 = v; i2 = c; }
    }
    #pragma unroll
    for (int off = 16; off; off >>= 1) {
        float ov1 = __shfl_down_sync(0xffffffffu, v1, off);
        int   oi1 = __shfl_down_sync(0xffffffffu, i1, off);
        float ov2 = __shfl_down_sync(0xffffffffu, v2, off);
        int   oi2 = __shfl_down_sync(0xffffffffu, i2, off);
        if (ov1 > v1) { v2 = v1; i2 = i1; v1 = ov1; i1 = oi1; if (ov2 > v2) { v2 = ov2; i2 = oi2; } }
        else if (ov1 > v2) { v2 = ov1; i2 = oi1; }
    }
    v1 = __shfl_sync(0xffffffffu, v1, 0);
    i1 = __shfl_sync(0xffffffffu, i1, 0);
    i2 = __shfl_sync(0xffffffffu, i2, 0);

    float ex[16]; float rs = 0.0f;
    #pragma unroll
    for (int t = 0; t < 16; t++) { ex[t] = expf(sc[t] - v1); rs += ex[t]; }
    #pragma unroll
    for (int o = 16; o; o >>= 1) rs += __shfl_xor_sync(0xffffffffu, rs, o);
    float inv_rs = 1.0f / rs;
    float* smrow = out_sm + n * 512;
    float* sqrow = out_sq + n * 512;
    #pragma unroll
    for (int t = 0; t < 16; t++) {
        int c = lane + t * 32;
        float sv = ex[t] * inv_rs;
        smrow[c] = sv;
        sqrow[c] = expf(sc[t] - cms[c]) * cssi[c];
        __nv_bfloat16 h, l; bf16split(sv, h, l);
        g_Ah[n * 512 + c] = h;           // reuse split buffers for GEMM2's A
        g_Al[n * 512 + c] = l;
    }
    if (lane == 0) {
        g_gi[n] = i1;
        g_w[n] = expf(v1 - cms[i1]);
        atomicAdd(&g_count[i1], 1);
    }

    const float* qrow = g_qr + n * 512;
    const float* pk = keys + (size_t)i1 * 512;
    const float* nk = keys + (size_t)i2 * 512;
    float comp = 0.0f, dp = 0.0f, dn = 0.0f;
    #pragma unroll
    for (int t = 0; t < 16; t++) {
        int c = lane + t * 32;
        float q = qrow[c], p = pk[c], gg = nk[c];
        float d0 = q - p; comp += d0 * d0;
        float d1 = d0 + 1e-6f; dp += d1 * d1;
        float d2 = (q - gg) + 1e-6f; dn += d2 * d2;
    }
    #pragma unroll
    for (int o = 16; o; o >>= 1) {
        comp += __shfl_xor_sync(0xffffffffu, comp, o);
        dp   += __shfl_xor_sync(0xffffffffu, dp, o);
        dn   += __shfl_xor_sync(0xffffffffu, dn, o);
    }
    if (lane == 0) {
        wcomp[warp] = (double)comp;
        wsep[warp] = (double)fmaxf(0.0f, sqrtf(dp) - sqrtf(dn) + 1.0f);
    }
    __syncthreads();
    if (threadIdx.x == 0) {
        double c = 0.0, s = 0.0;
        for (int wv = 0; wv < 8; wv++) { c += wcomp[wv]; s += wsep[wv]; }
        atomicAdd(&g_comp, c);
        atomicAdd(&g_sep, s);
    }
}

// ---------------- counting sort of rows by gi ----------------
__global__ void __launch_bounds__(512) k_scan() {
    __shared__ int s[512];
    int t = threadIdx.x;
    int v = g_count[t];
    s[t] = v;
    __syncthreads();
    for (int off = 1; off < 512; off <<= 1) {
        int add = (t >= off) ? s[t - off] : 0;
        __syncthreads();
        s[t] += add;
        __syncthreads();
    }
    g_offset[t + 1] = s[t];
    if (t == 0) g_offset[0] = 0;
    g_cursor[t] = s[t] - v;
}

__global__ void k_scatter() {
    for (int n = blockIdx.x * blockDim.x + threadIdx.x; n < NTOT; n += gridDim.x * blockDim.x) {
        int m = g_gi[n];
        int idx = atomicAdd(&g_cursor[m], 1);
        g_list[idx] = n;
    }
}

// ---------------- memory update: segment sum + l2norm ----------------
__global__ void __launch_bounds__(512) k_update(const float* __restrict__ keys,
                                                float* __restrict__ outUM) {
    int m = blockIdx.x;
    int t = threadIdx.x;
    __shared__ int sln[256];
    __shared__ float slw[256];
    __shared__ float red[16];
    __shared__ float rn_s;
    int beg = g_offset[m], end = g_offset[m + 1];
    float acc = 0.0f;
    for (int base = beg; base < end; base += 256) {
        int cnt = min(256, end - base);
        __syncthreads();
        if (t < cnt) { int n = g_list[base + t]; sln[t] = n; slw[t] = g_w[n]; }
        __syncthreads();
        for (int i = 0; i < cnt; i++)
            acc += slw[i] * g_qr[(size_t)sln[i] * 512 + t];
    }
    float um = acc + keys[(size_t)m * 512 + t];
    float ss = um * um;
    #pragma unroll
    for (int o = 16; o; o >>= 1) ss += __shfl_xor_sync(0xffffffffu, ss, o);
    if ((t & 31) == 0) red[t >> 5] = ss;
    __syncthreads();
    if (t == 0) {
        float x = 0.0f;
        for (int i = 0; i < 16; i++) x += red[i];
        rn_s = 1.0f / fmaxf(sqrtf(x), 1e-12f);
    }
    __syncthreads();
    outUM[(size_t)m * 512 + t] = um * rn_s;
}

// ---------------- losses ----------------
__global__ void k_finalize(float* __restrict__ out) {
    out[OFF_SEP] = (float)(g_sep / (double)NTOT);
    out[OFF_COMP] = (float)(g_comp / ((double)NTOT * (double)CDIM));
}

// ---------------- launch ----------------
extern "C" void kernel_launch(void* const* d_in, const int* in_sizes, int n_in,
                              void* d_out, int out_size) {
    const float* query = (const float*)d_in[0];
    const float* keys  = (const float*)d_in[1];
    float* out = (float*)d_out;

    float* p_score = nullptr;
    __nv_bfloat16 *p_Ah = nullptr, *p_Al = nullptr, *p_Bh = nullptr, *p_Bl = nullptr;
    __nv_bfloat16 *p_BTh = nullptr, *p_BTl = nullptr;
    cudaGetSymbolAddress((void**)&p_score, g_score);
    cudaGetSymbolAddress((void**)&p_Ah, g_Ah);
    cudaGetSymbolAddress((void**)&p_Al, g_Al);
    cudaGetSymbolAddress((void**)&p_Bh, g_Bh);
    cudaGetSymbolAddress((void**)&p_Bl, g_Bl);
    cudaGetSymbolAddress((void**)&p_BTh, g_BTh);
    cudaGetSymbolAddress((void**)&p_BTl, g_BTl);

    cudaFuncSetAttribute(k_mma<0>, cudaFuncAttributeMaxDynamicSharedMemorySize, 65536);
    cudaFuncSetAttribute(k_mma<1>, cudaFuncAttributeMaxDynamicSharedMemorySize, 65536);

    k_init<<<2, 256>>>();
    k_normalize<<<NTOT / 16, 256>>>(query, out);
    k_prepkeys<<<dim3(16, 16), dim3(32, 8)>>>(keys);
    k_mma<0><<<dim3(4, NTOT / 128), 256, 65536>>>(p_Ah, p_Al, p_Bh, p_Bl, p_score);
    k_colstat<<<NTOT / 128, 512>>>();
    k_row<<<NTOT / 8, 256>>>(out + OFF_SQ, out + OFF_SM, keys);
    k_scan<<<1, 512>>>();
    k_scatter<<<64, 256>>>();
    k_update<<<MDIM, 512>>>(keys, out + OFF_UM);
    k_mma<1><<<dim3(4, NTOT / 128), 256, 65536>>>(p_Ah, p_Al, p_BTh, p_BTl, out);
    k_finalize<<<1, 1>>>(out);
}